// round 11
// baseline (speedup 1.0000x reference)
#include <cuda_runtime.h>
#include <cuda_fp16.h>
#include <math.h>
#include <stdint.h>

#define Bn 16384
#define Ln 50
#define Dn 128
#define Fn 6
#define CINn 2688
#define H1N 512
#define H2N 256
#define NB 4

// ---------------- scratch (static device globals) ---------------------------
__device__ __align__(16) __half g_s  [Bn * Fn * Dn];   // fp16 SE-scaled feats
__device__ __align__(16) __half g_c  [Bn * CINn];      // fp16 activations
__device__ __align__(16) __half g_h1 [Bn * H1N];
__device__ __align__(16) float g_h2 [Bn * H2N];
__device__ __align__(16) __half g_w1t[H1N * CINn];     // fp16 weights (transposed)
__device__ __align__(16) __half g_w2t[H2N * H1N];
__device__ __align__(16) __half g_wb [5 * Dn * Dn];    // bi_W as [f][e][d]

// ---------------- PTX helpers (sm_80-level only) -----------------------------
__device__ __forceinline__ uint32_t smem_u32(const void* p) {
    uint32_t a;
    asm("{ .reg .u64 t; cvta.to.shared.u64 t, %1; cvt.u32.u64 %0, t; }" : "=r"(a) : "l"(p));
    return a;
}
__device__ __forceinline__ void cp16(uint32_t dst, const void* src) {
    asm volatile("cp.async.cg.shared.global [%0], [%1], 16;" :: "r"(dst), "l"(src));
}
__device__ __forceinline__ void cp_commit() {
    asm volatile("cp.async.commit_group;" ::: "memory");
}
template <int N>
__device__ __forceinline__ void cp_wait() {
    asm volatile("cp.async.wait_group %0;" :: "n"(N) : "memory");
}
__device__ __forceinline__ void ldsm4(uint32_t* r, uint32_t addr) {
    asm volatile("ldmatrix.sync.aligned.m8n8.x4.shared.b16 {%0,%1,%2,%3}, [%4];"
                 : "=r"(r[0]), "=r"(r[1]), "=r"(r[2]), "=r"(r[3]) : "r"(addr));
}
__device__ __forceinline__ void mma_fp16(float* d, const uint32_t* a, const uint32_t* b) {
    asm volatile(
        "mma.sync.aligned.m16n8k16.row.col.f32.f16.f16.f32 "
        "{%0,%1,%2,%3}, {%4,%5,%6,%7}, {%8,%9}, {%0,%1,%2,%3};"
        : "+f"(d[0]), "+f"(d[1]), "+f"(d[2]), "+f"(d[3])
        : "r"(a[0]), "r"(a[1]), "r"(a[2]), "r"(a[3]), "r"(b[0]), "r"(b[1]));
}

// ---------------- K1: fused features + GAT + SE, NB samples per block --------
__global__ __launch_bounds__(128) void k_feat_gnn(
    const int* __restrict__ item_id, const float* __restrict__ item_mm,
    const int* __restrict__ likes, const int* __restrict__ views,
    const int* __restrict__ item_seq, const float* __restrict__ item_emb,
    const float* __restrict__ cate_emb, const float* __restrict__ mm_w,
    const float* __restrict__ mm_b, const float* __restrict__ ln_g,
    const float* __restrict__ ln_b,
    const float* __restrict__ gnn_W, const float* __restrict__ gnn_a,
    const float* __restrict__ se_w1, const float* __restrict__ se_b1,
    const float* __restrict__ se_w2, const float* __restrict__ se_b2)
{
    const int b0 = blockIdx.x * NB;
    const int t = threadIdx.x;
    const int lane = t & 31, w = t >> 5;
    const int h = w;
    __shared__ float sm[NB][Dn];
    __shared__ int sseq[NB][Ln];
    __shared__ float xs[NB][Fn * Dn];
    __shared__ float red[NB][8];
    __shared__ float red2[NB][4 * Fn];

    for (int i = t; i < NB * Dn; i += 128) sm[i >> 7][i & 127] = item_mm[b0 * Dn + i];
    for (int i = t; i < NB * Ln; i += 128) sseq[i / Ln][i % Ln] = item_seq[b0 * Ln + i];
    __syncthreads();

    // ---- mm GEMM: weights hoisted once, reused across NB samples ----
    float y[NB];
    {
        float bias = mm_b[t];
        #pragma unroll
        for (int s = 0; s < NB; s++) y[s] = bias;
        const float* Wc = mm_w + t;
        #pragma unroll 1
        for (int c = 0; c < 4; c++) {
            float wv[32];
            #pragma unroll
            for (int q = 0; q < 32; q++) wv[q] = Wc[(c * 32 + q) * Dn];
            #pragma unroll
            for (int s = 0; s < NB; s++) {
                const float4* xv = reinterpret_cast<const float4*>(&sm[s][c * 32]);
                float a = y[s];
                #pragma unroll
                for (int q8 = 0; q8 < 8; q8++) {
                    float4 v = xv[q8];
                    a = fmaf(v.x, wv[q8 * 4 + 0], a);
                    a = fmaf(v.y, wv[q8 * 4 + 1], a);
                    a = fmaf(v.z, wv[q8 * 4 + 2], a);
                    a = fmaf(v.w, wv[q8 * 4 + 3], a);
                }
                y[s] = a;
            }
        }
    }

    // ---- LayerNorm + GELU per sample ----
    #pragma unroll
    for (int s = 0; s < NB; s++) {
        float s1 = y[s], s2 = y[s] * y[s];
        #pragma unroll
        for (int o = 16; o; o >>= 1) {
            s1 += __shfl_xor_sync(0xffffffffu, s1, o);
            s2 += __shfl_xor_sync(0xffffffffu, s2, o);
        }
        if (!lane) { red[s][w] = s1; red[s][4 + w] = s2; }
    }
    __syncthreads();
    float img[NB];
    {
        float lng = ln_g[t], lnb = ln_b[t];
        #pragma unroll
        for (int s = 0; s < NB; s++) {
            float mu = (red[s][0] + red[s][1] + red[s][2] + red[s][3]) * (1.f / Dn);
            float m2 = (red[s][4] + red[s][5] + red[s][6] + red[s][7]) * (1.f / Dn);
            float var = m2 - mu * mu;
            float yn = (y[s] - mu) * rsqrtf(var + 1e-5f) * lng + lnb;
            img[s] = 0.5f * yn * (1.f + erff(yn * 0.70710678118654752f));
        }
    }

    // ---- masked seq mean, MLP across samples (item_emb[0] == 0) ----
    float hs[NB];
    int cnt[NB];
    #pragma unroll
    for (int s = 0; s < NB; s++) { hs[s] = 0.f; cnt[s] = 0; }
    #pragma unroll 5
    for (int l = 0; l < Ln; l++) {
        #pragma unroll
        for (int s = 0; s < NB; s++) {
            int id = sseq[s][l];
            hs[s] += item_emb[(size_t)id * Dn + t];
            cnt[s] += (id != 0);
        }
    }

    #pragma unroll
    for (int s = 0; s < NB; s++) {
        int b = b0 + s;
        xs[s][0 * Dn + t] = 0.f;
        xs[s][1 * Dn + t] = cate_emb[likes[b] * Dn + t];
        xs[s][2 * Dn + t] = cate_emb[views[b] * Dn + t];
        xs[s][3 * Dn + t] = item_emb[(size_t)item_id[b] * Dn + t];
        xs[s][4 * Dn + t] = img[s];
        xs[s][5 * Dn + t] = hs[s] / fmaxf((float)cnt[s], 1.f);
    }
    __syncthreads();

    // ---- GAT projection: hp[s][n] = sum_i xs[s][n][i] * W[h][i][lane] ----
    float hp[NB][Fn];
    #pragma unroll
    for (int s = 0; s < NB; s++)
        #pragma unroll
        for (int n = 0; n < Fn; n++) hp[s][n] = 0.f;
    {
        const float* Wh = gnn_W + h * (Dn * 32) + lane;
        #pragma unroll 1
        for (int c = 0; c < 4; c++) {
            float wv[32];
            #pragma unroll
            for (int q = 0; q < 32; q++) wv[q] = Wh[(c * 32 + q) * 32];
            #pragma unroll
            for (int s = 0; s < NB; s++) {
                #pragma unroll
                for (int n = 0; n < Fn; n++) {
                    const float4* xv = reinterpret_cast<const float4*>(&xs[s][n * Dn + c * 32]);
                    float a = hp[s][n];
                    #pragma unroll
                    for (int q8 = 0; q8 < 8; q8++) {
                        float4 v = xv[q8];
                        a = fmaf(v.x, wv[q8 * 4 + 0], a);
                        a = fmaf(v.y, wv[q8 * 4 + 1], a);
                        a = fmaf(v.z, wv[q8 * 4 + 2], a);
                        a = fmaf(v.w, wv[q8 * 4 + 3], a);
                    }
                    hp[s][n] = a;
                }
            }
        }
    }

    const float a1 = gnn_a[h * 64 + lane];
    const float a2 = gnn_a[h * 64 + 32 + lane];

    #pragma unroll 1
    for (int s = 0; s < NB; s++) {
        float ei[Fn], ej[Fn];
        #pragma unroll
        for (int n = 0; n < Fn; n++) {
            float v1 = hp[s][n] * a1, v2 = hp[s][n] * a2;
            #pragma unroll
            for (int o = 16; o; o >>= 1) {
                v1 += __shfl_xor_sync(0xffffffffu, v1, o);
                v2 += __shfl_xor_sync(0xffffffffu, v2, o);
            }
            ei[n] = v1; ej[n] = v2;
        }

        float gnn[Fn];
        #pragma unroll
        for (int n = 0; n < Fn; n++) {
            float em[Fn], mx = -1e30f;
            #pragma unroll
            for (int m = 0; m < Fn; m++) {
                float e = ei[n] + ej[m];
                e = e > 0.f ? e : 0.2f * e;
                em[m] = e; mx = fmaxf(mx, e);
            }
            float ss = 0.f;
            #pragma unroll
            for (int m = 0; m < Fn; m++) { em[m] = expf(em[m] - mx); ss += em[m]; }
            float inv = 1.f / ss, acc = 0.f;
            #pragma unroll
            for (int m = 0; m < Fn; m++) acc = fmaf(em[m], hp[s][m], acc);
            float hn = acc * inv + xs[s][n * Dn + t];
            gnn[n] = hn > 0.f ? hn : expm1f(hn);
        }

        #pragma unroll
        for (int n = 0; n < Fn; n++) {
            float v = gnn[n];
            #pragma unroll
            for (int o = 16; o; o >>= 1) v += __shfl_xor_sync(0xffffffffu, v, o);
            if (!lane) red2[s][h * Fn + n] = v;
        }
        __syncthreads();

        float wv[Fn];
        {
            float z[Fn];
            #pragma unroll
            for (int n = 0; n < Fn; n++)
                z[n] = (red2[s][0 * Fn + n] + red2[s][1 * Fn + n] +
                        red2[s][2 * Fn + n] + red2[s][3 * Fn + n]) * (1.f / Dn);
            float a[3];
            #pragma unroll
            for (int k = 0; k < 3; k++) {
                float v = se_b1[k];
                #pragma unroll
                for (int n = 0; n < Fn; n++) v = fmaf(z[n], se_w1[n * 3 + k], v);
                a[k] = fmaxf(v, 0.f);
            }
            #pragma unroll
            for (int f = 0; f < Fn; f++) {
                float v = se_b2[f];
                #pragma unroll
                for (int k = 0; k < 3; k++) v = fmaf(a[k], se_w2[k * 6 + f], v);
                wv[f] = 1.f / (1.f + expf(-v));
            }
        }

        __half* ch = g_c + (size_t)(b0 + s) * CINn;
        __half* sb = g_s + (size_t)(b0 + s) * Fn * Dn;
        #pragma unroll
        for (int n = 0; n < Fn; n++) {
            float v = gnn[n];
            ch[n * Dn + t] = __float2half(v);
            sb[n * Dn + t] = __float2half(v * wv[n]);
        }
        __syncthreads();
    }
}

// ---------------- weight prep: transpose + fp16 ------------------------------
__global__ __launch_bounds__(256) void k_wt(
    const float* __restrict__ W, __half* __restrict__ T, int K, int N)
{
    int idx = blockIdx.x * 256 + threadIdx.x;
    if (idx >= K * N) return;
    int k = idx / N, n = idx - k * N;
    T[(size_t)n * K + k] = __float2half(W[idx]);
}
// bi_W[f][d][e] -> [f][n=e][k=d], fp16
__global__ __launch_bounds__(256) void k_wbi(const float* __restrict__ W)
{
    int idx = blockIdx.x * 256 + threadIdx.x;
    if (idx >= 5 * 128 * 128) return;
    int f = idx >> 14, rem = idx & 16383;
    int d = rem >> 7, e = rem & 127;
    g_wb[(f << 14) + e * 128 + d] = __float2half(W[idx]);
}

// ---------------- shared GEMM constants --------------------------------------
#define BK 32
#define ROWB 80u

// ---------------- k_mma128: BN=128 (bilinear + fused pairs) ------------------
#define BM 128
#define BN 128
#define OFF_A  0u
#define OFF_B  10240u
#define STAGEB 20480u
#define NSTAGE 4
#define SMEM_MMA (NSTAGE * STAGEB)

__global__ __launch_bounds__(256, 1) void k_mma128(
    const __half* __restrict__ A, const __half* __restrict__ B,
    int K, int lda, long az, long bz)
{
    extern __shared__ char smem[];
    const uint32_t sbase = smem_u32(smem);
    const int tid = threadIdx.x;
    const int lane = tid & 31, wid = tid >> 5;
    const int wm = wid >> 2, wn = wid & 3;
    const int bm = blockIdx.y * BM, bn = blockIdx.x * BN;
    const int z = blockIdx.z;
    A += (size_t)z * az;
    B += (size_t)z * bz;

    float acc[4][4][4];
    #pragma unroll
    for (int mi = 0; mi < 4; mi++)
        #pragma unroll
        for (int ni = 0; ni < 4; ni++)
            #pragma unroll
            for (int q = 0; q < 4; q++) acc[mi][ni][q] = 0.f;

    const uint32_t a_base = (uint32_t)(wm * 64 + (lane & 15)) * ROWB + (uint32_t)((lane >> 4) * 16);
    const uint32_t b_base = (uint32_t)(wn * 32 + (lane & 7) + ((lane >> 4) << 3)) * ROWB
                          + (uint32_t)(((lane >> 3) & 1) * 16);

    const int nIter = K / BK;

    auto load_stage = [&](int buf, int k0) {
        uint32_t base = sbase + (uint32_t)buf * STAGEB;
        #pragma unroll
        for (int half = 0; half < 2; half++) {
            int e = tid + half * 256;
            int r = e >> 2, c = e & 3;
            uint32_t off = (uint32_t)r * ROWB + (uint32_t)c * 16;
            cp16(base + OFF_A + off, A + (size_t)(bm + r) * lda + k0 + c * 8);
            cp16(base + OFF_B + off, B + (size_t)(bn + r) * K   + k0 + c * 8);
        }
    };

    load_stage(0, 0);
    cp_commit();
    load_stage(1, BK);
    cp_commit();
    load_stage(2, 2 * BK);
    cp_commit();

    for (int it = 0; it < nIter; it++) {
        if (it + 3 < nIter) {
            load_stage((it + 3) & 3, (it + 3) * BK);
            cp_commit();
            cp_wait<3>();
        } else if (it + 2 < nIter) {
            cp_wait<2>();
        } else if (it + 1 < nIter) {
            cp_wait<1>();
        } else {
            cp_wait<0>();
        }
        __syncthreads();

        uint32_t base = sbase + (uint32_t)(it & 3) * STAGEB;
        #pragma unroll
        for (int ks = 0; ks < 2; ks++) {
            uint32_t koff = (uint32_t)ks * 32;
            uint32_t a[4][4], bb[2][4];
            #pragma unroll
            for (int mi = 0; mi < 4; mi++)
                ldsm4(a[mi], base + OFF_A + a_base + (uint32_t)mi * 16 * ROWB + koff);
            #pragma unroll
            for (int nq = 0; nq < 2; nq++)
                ldsm4(bb[nq], base + OFF_B + b_base + (uint32_t)nq * 16 * ROWB + koff);
            #pragma unroll
            for (int mi = 0; mi < 4; mi++)
                #pragma unroll
                for (int ni = 0; ni < 4; ni++)
                    mma_fp16(acc[mi][ni], a[mi], &bb[ni >> 1][(ni & 1) * 2]);
        }
        __syncthreads();
    }

    // fused pairs epilogue: c[row, pair(z,j), col] = vid * s[row, j, col]
    const int poff = z * (11 - z) / 2;
    #pragma unroll
    for (int ni = 0; ni < 4; ni++) {
        int col = bn + wn * 32 + ni * 8 + (lane & 3) * 2;
        #pragma unroll
        for (int mi = 0; mi < 4; mi++) {
            int r0 = bm + wm * 64 + mi * 16 + (lane >> 2);
            #pragma unroll
            for (int half = 0; half < 2; half++) {
                int row = r0 + half * 8;
                float v0 = acc[mi][ni][half * 2 + 0];
                float v1 = acc[mi][ni][half * 2 + 1];
                const __half* sb = g_s + (size_t)row * (Fn * Dn);
                __half* cp = g_c + (size_t)row * CINn + Fn * Dn;
                for (int j = z + 1; j < Fn; j++) {
                    int p = poff + j - z - 1;
                    float s0 = __half2float(sb[j * Dn + col]);
                    float s1 = __half2float(sb[j * Dn + col + 1]);
                    cp[p * Dn + col]     = __float2half(v0 * s0);
                    cp[p * Dn + col + 1] = __float2half(v1 * s1);
                }
            }
        }
    }
}

// ---------------- k_mma256: BN=256, warp tile 64x64 (MLP layers) -------------
#define BM2 128
#define BN2 256
#define OFF_A2  0u
#define OFF_B2  10240u
#define STAGEB2 30720u
#define NSTAGE2 4
#define SMEM_MMA2 (NSTAGE2 * STAGEB2)

__global__ __launch_bounds__(256, 1) void k_mma256(
    const __half* __restrict__ A, const __half* __restrict__ B,
    int K,
    float* __restrict__ outf, __half* __restrict__ oh, int ldc,
    const float* __restrict__ bias, const float* __restrict__ bng,
    const float* __restrict__ bnb, int mode)
{
    extern __shared__ char smem[];
    const uint32_t sbase = smem_u32(smem);
    const int tid = threadIdx.x;
    const int lane = tid & 31, wid = tid >> 5;
    const int wm = wid >> 2, wn = wid & 3;          // 2(M) x 4(N), warp 64x64
    const int bm = blockIdx.y * BM2, bn = blockIdx.x * BN2;

    float acc[4][8][4];
    #pragma unroll
    for (int mi = 0; mi < 4; mi++)
        #pragma unroll
        for (int ni = 0; ni < 8; ni++)
            #pragma unroll
            for (int q = 0; q < 4; q++) acc[mi][ni][q] = 0.f;

    const uint32_t a_base = (uint32_t)(wm * 64 + (lane & 15)) * ROWB + (uint32_t)((lane >> 4) * 16);
    const uint32_t b_base = (uint32_t)(wn * 64 + (lane & 7) + ((lane >> 4) << 3)) * ROWB
                          + (uint32_t)(((lane >> 3) & 1) * 16);

    const int nIter = K / BK;

    auto load_stage = [&](int buf, int k0) {
        uint32_t base = sbase + (uint32_t)buf * STAGEB2;
        #pragma unroll
        for (int half = 0; half < 2; half++) {
            int e = tid + half * 256;
            int r = e >> 2, c = e & 3;
            uint32_t off = (uint32_t)r * ROWB + (uint32_t)c * 16;
            cp16(base + OFF_A2 + off, A + (size_t)(bm + r) * K + k0 + c * 8);
        }
        #pragma unroll
        for (int half = 0; half < 4; half++) {
            int e = tid + half * 256;
            int r = e >> 2, c = e & 3;
            uint32_t off = (uint32_t)r * ROWB + (uint32_t)c * 16;
            cp16(base + OFF_B2 + off, B + (size_t)(bn + r) * K + k0 + c * 8);
        }
    };

    load_stage(0, 0);
    cp_commit();
    load_stage(1, BK);
    cp_commit();
    load_stage(2, 2 * BK);
    cp_commit();

    for (int it = 0; it < nIter; it++) {
        if (it + 3 < nIter) {
            load_stage((it + 3) & 3, (it + 3) * BK);
            cp_commit();
            cp_wait<3>();
        } else if (it + 2 < nIter) {
            cp_wait<2>();
        } else if (it + 1 < nIter) {
            cp_wait<1>();
        } else {
            cp_wait<0>();
        }
        __syncthreads();

        uint32_t base = sbase + (uint32_t)(it & 3) * STAGEB2;
        #pragma unroll
        for (int ks = 0; ks < 2; ks++) {
            uint32_t koff = (uint32_t)ks * 32;
            uint32_t a[4][4], bb[4][4];
            #pragma unroll
            for (int mi = 0; mi < 4; mi++)
                ldsm4(a[mi], base + OFF_A2 + a_base + (uint32_t)mi * 16 * ROWB + koff);
            #pragma unroll
            for (int nq = 0; nq < 4; nq++)
                ldsm4(bb[nq], base + OFF_B2 + b_base + (uint32_t)nq * 16 * ROWB + koff);
            #pragma unroll
            for (int mi = 0; mi < 4; mi++)
                #pragma unroll
                for (int ni = 0; ni < 8; ni++)
                    mma_fp16(acc[mi][ni], a[mi], &bb[ni >> 1][(ni & 1) * 2]);
        }
        __syncthreads();
    }

    const float bnscale = 0.999995000037499688f;  // 1/sqrt(1+1e-5)
    #pragma unroll
    for (int ni = 0; ni < 8; ni++) {
        int col = bn + wn * 64 + ni * 8 + (lane & 3) * 2;
        float bi0 = bias[col],         bi1 = bias[col + 1];
        float g0 = bng[col] * bnscale, g1 = bng[col + 1] * bnscale;
        float bb0 = bnb[col],          bb1 = bnb[col + 1];
        #pragma unroll
        for (int mi = 0; mi < 4; mi++) {
            int r0 = bm + wm * 64 + mi * 16 + (lane >> 2);
            #pragma unroll
            for (int half = 0; half < 2; half++) {
                int row = r0 + half * 8;
                float v0 = acc[mi][ni][half * 2 + 0];
                float v1 = acc[mi][ni][half * 2 + 1];
                v0 = (v0 + bi0) * g0 + bb0;
                v1 = (v1 + bi1) * g1 + bb1;
                v0 = 0.5f * v0 * (1.f + erff(v0 * 0.70710678118654752f));
                v1 = 0.5f * v1 * (1.f + erff(v1 * 0.70710678118654752f));
                if (mode == 2) {
                    outf[(size_t)row * ldc + col]     = v0;
                    outf[(size_t)row * ldc + col + 1] = v1;
                } else {
                    oh[(size_t)row * ldc + col]     = __float2half(v0);
                    oh[(size_t)row * ldc + col + 1] = __float2half(v1);
                }
            }
        }
    }
}

// ---------------- K5: final dot + sigmoid ------------------------------------
__global__ __launch_bounds__(256) void k_final(
    const float* __restrict__ w3, const float* __restrict__ b3,
    float* __restrict__ out)
{
    int warp = threadIdx.x >> 5, lane = threadIdx.x & 31;
    int b = blockIdx.x * 8 + warp;
    const float* hh = g_h2 + (size_t)b * H2N;
    float acc = 0.f;
    #pragma unroll
    for (int i = 0; i < 8; i++) acc = fmaf(hh[lane + i * 32], w3[lane + i * 32], acc);
    #pragma unroll
    for (int o = 16; o; o >>= 1) acc += __shfl_xor_sync(0xffffffffu, acc, o);
    if (!lane) out[b] = 1.f / (1.f + expf(-(acc + b3[0])));
}

// ---------------- launch -----------------------------------------------------
extern "C" void kernel_launch(void* const* d_in, const int* in_sizes, int n_in,
                              void* d_out, int out_size)
{
    const int*   item_id  = (const int*)  d_in[0];
    const float* item_mm  = (const float*)d_in[1];
    const int*   likes    = (const int*)  d_in[2];
    const int*   views    = (const int*)  d_in[3];
    const int*   item_seq = (const int*)  d_in[4];
    const float* item_emb = (const float*)d_in[5];
    const float* cate_emb = (const float*)d_in[6];
    const float* mm_w     = (const float*)d_in[7];
    const float* mm_b     = (const float*)d_in[8];
    const float* ln_g     = (const float*)d_in[9];
    const float* ln_b     = (const float*)d_in[10];
    const float* gnn_W    = (const float*)d_in[11];
    const float* gnn_a    = (const float*)d_in[12];
    const float* se_w1    = (const float*)d_in[13];
    const float* se_b1    = (const float*)d_in[14];
    const float* se_w2    = (const float*)d_in[15];
    const float* se_b2    = (const float*)d_in[16];
    const float* bi_W     = (const float*)d_in[17];
    const float* w1       = (const float*)d_in[18];
    const float* b1       = (const float*)d_in[19];
    const float* bn1g     = (const float*)d_in[20];
    const float* bn1b     = (const float*)d_in[21];
    const float* w2       = (const float*)d_in[22];
    const float* b2       = (const float*)d_in[23];
    const float* bn2g     = (const float*)d_in[24];
    const float* bn2b     = (const float*)d_in[25];
    const float* w3       = (const float*)d_in[26];
    const float* b3       = (const float*)d_in[27];
    float* out = (float*)d_out;

    float *ph2;
    __half *ps, *pc, *ph1, *pw1, *pw2, *pwb;
    cudaGetSymbolAddress((void**)&ps,   g_s);
    cudaGetSymbolAddress((void**)&ph2,  g_h2);
    cudaGetSymbolAddress((void**)&pc,   g_c);
    cudaGetSymbolAddress((void**)&ph1,  g_h1);
    cudaGetSymbolAddress((void**)&pw1,  g_w1t);
    cudaGetSymbolAddress((void**)&pw2,  g_w2t);
    cudaGetSymbolAddress((void**)&pwb,  g_wb);

    cudaFuncSetAttribute(k_mma128, cudaFuncAttributeMaxDynamicSharedMemorySize, SMEM_MMA);
    cudaFuncSetAttribute(k_mma256, cudaFuncAttributeMaxDynamicSharedMemorySize, SMEM_MMA2);

    // weight prep (fp16 transpose)
    k_wt<<<(CINn * H1N + 255) / 256, 256>>>(w1, pw1, CINn, H1N);
    k_wt<<<(H1N * H2N + 255) / 256, 256>>>(w2, pw2, H1N, H2N);
    k_wbi<<<(5 * 128 * 128 + 255) / 256, 256>>>(bi_W);

    // fused features + GNN + SE (NB samples per block)
    k_feat_gnn<<<Bn / NB, 128>>>(item_id, item_mm, likes, views, item_seq,
                                 item_emb, cate_emb, mm_w, mm_b, ln_g, ln_b,
                                 gnn_W, gnn_a, se_w1, se_b1, se_w2, se_b2);

    // bilinear + fused pairs: z = field i; writes c[:, 768:] directly
    {
        dim3 grid(1, Bn / BM, 5);
        k_mma128<<<grid, 256, SMEM_MMA>>>(ps, pwb, Dn, Fn * Dn, Dn, (long)Dn * Dn);
    }

    // layer 1: c @ w1 (+bias,bn,gelu) -> h1 (fp16)
    {
        dim3 grid(H1N / BN2, Bn / BM2, 1);
        k_mma256<<<grid, 256, SMEM_MMA2>>>(pc, pw1, CINn,
                                           nullptr, ph1, H1N, b1, bn1g, bn1b, 1);
    }
    // layer 2: h1 @ w2 (+bias,bn,gelu) -> h2 (fp32)
    {
        dim3 grid(H2N / BN2, Bn / BM2, 1);
        k_mma256<<<grid, 256, SMEM_MMA2>>>(ph1, pw2, H1N,
                                           ph2, nullptr, H2N, b2, bn2g, bn2b, 2);
    }
    k_final<<<Bn / 8, 256>>>(w3, b3, out);
}

// round 12
// speedup vs baseline: 1.0383x; 1.0383x over previous
#include <cuda_runtime.h>
#include <cuda_fp16.h>
#include <math.h>
#include <stdint.h>

#define Bn 16384
#define Ln 50
#define Dn 128
#define Fn 6
#define CINn 2688
#define H1N 512
#define H2N 256

// ---------------- scratch (static device globals) ---------------------------
__device__ __align__(16) __half g_s  [Bn * Fn * Dn];   // fp16 SE-scaled feats
__device__ __align__(16) __half g_c  [Bn * CINn];      // fp16 activations
__device__ __align__(16) __half g_h1 [Bn * H1N];
__device__ __align__(16) float g_h2 [Bn * H2N];
__device__ __align__(16) __half g_w1t[H1N * CINn];     // fp16 weights (transposed)
__device__ __align__(16) __half g_w2t[H2N * H1N];
__device__ __align__(16) __half g_wb [5 * Dn * Dn];    // bi_W as [f][e][d]

// ---------------- PTX helpers (sm_80-level only) -----------------------------
__device__ __forceinline__ uint32_t smem_u32(const void* p) {
    uint32_t a;
    asm("{ .reg .u64 t; cvta.to.shared.u64 t, %1; cvt.u32.u64 %0, t; }" : "=r"(a) : "l"(p));
    return a;
}
__device__ __forceinline__ void cp16(uint32_t dst, const void* src) {
    asm volatile("cp.async.cg.shared.global [%0], [%1], 16;" :: "r"(dst), "l"(src));
}
__device__ __forceinline__ void cp_commit() {
    asm volatile("cp.async.commit_group;" ::: "memory");
}
template <int N>
__device__ __forceinline__ void cp_wait() {
    asm volatile("cp.async.wait_group %0;" :: "n"(N) : "memory");
}
__device__ __forceinline__ void ldsm4(uint32_t* r, uint32_t addr) {
    asm volatile("ldmatrix.sync.aligned.m8n8.x4.shared.b16 {%0,%1,%2,%3}, [%4];"
                 : "=r"(r[0]), "=r"(r[1]), "=r"(r[2]), "=r"(r[3]) : "r"(addr));
}
__device__ __forceinline__ void mma_fp16(float* d, const uint32_t* a, const uint32_t* b) {
    asm volatile(
        "mma.sync.aligned.m16n8k16.row.col.f32.f16.f16.f32 "
        "{%0,%1,%2,%3}, {%4,%5,%6,%7}, {%8,%9}, {%0,%1,%2,%3};"
        : "+f"(d[0]), "+f"(d[1]), "+f"(d[2]), "+f"(d[3])
        : "r"(a[0]), "r"(a[1]), "r"(a[2]), "r"(a[3]), "r"(b[0]), "r"(b[1]));
}

// ---------------- K1: fused features + GAT + SE (R10 single-sample) ----------
__global__ __launch_bounds__(128) void k_feat_gnn(
    const int* __restrict__ item_id, const float* __restrict__ item_mm,
    const int* __restrict__ likes, const int* __restrict__ views,
    const int* __restrict__ item_seq, const float* __restrict__ item_emb,
    const float* __restrict__ cate_emb, const float* __restrict__ mm_w,
    const float* __restrict__ mm_b, const float* __restrict__ ln_g,
    const float* __restrict__ ln_b,
    const float* __restrict__ gnn_W, const float* __restrict__ gnn_a,
    const float* __restrict__ se_w1, const float* __restrict__ se_b1,
    const float* __restrict__ se_w2, const float* __restrict__ se_b2)
{
    int b = blockIdx.x, t = threadIdx.x;
    int lane = t & 31, w = t >> 5;
    int h = w;
    __shared__ float xs[Fn * Dn];
    __shared__ float sm[Dn];
    __shared__ float red[8];
    __shared__ float red2[4 * Fn];
    __shared__ int sseq[Ln];

    sm[t] = item_mm[b * Dn + t];
    if (t < Ln) sseq[t] = item_seq[b * Ln + t];
    __syncthreads();

    float y = mm_b[t];
    {
        const float* Wc = mm_w + t;
        #pragma unroll
        for (int c = 0; c < 4; c++) {
            float wv[32];
            #pragma unroll
            for (int q = 0; q < 32; q++) wv[q] = Wc[(c * 32 + q) * Dn];
            const float4* xv = reinterpret_cast<const float4*>(&sm[c * 32]);
            #pragma unroll
            for (int q8 = 0; q8 < 8; q8++) {
                float4 v = xv[q8];
                y = fmaf(v.x, wv[q8 * 4 + 0], y);
                y = fmaf(v.y, wv[q8 * 4 + 1], y);
                y = fmaf(v.z, wv[q8 * 4 + 2], y);
                y = fmaf(v.w, wv[q8 * 4 + 3], y);
            }
        }
    }

    float s1 = y, s2 = y * y;
    #pragma unroll
    for (int o = 16; o; o >>= 1) {
        s1 += __shfl_xor_sync(0xffffffffu, s1, o);
        s2 += __shfl_xor_sync(0xffffffffu, s2, o);
    }
    if (!lane) { red[w] = s1; red[4 + w] = s2; }
    __syncthreads();
    float mu = (red[0] + red[1] + red[2] + red[3]) * (1.f / Dn);
    float m2 = (red[4] + red[5] + red[6] + red[7]) * (1.f / Dn);
    float var = m2 - mu * mu;
    float yn = (y - mu) * rsqrtf(var + 1e-5f) * ln_g[t] + ln_b[t];
    float img = 0.5f * yn * (1.f + erff(yn * 0.70710678118654752f));

    // branch-free masked mean: item_emb[0] == 0 by construction
    float hs = 0.f;
    int cnt = 0;
    #pragma unroll 10
    for (int l = 0; l < Ln; l++) {
        int id = sseq[l];
        hs += item_emb[(size_t)id * Dn + t];
        cnt += (id != 0);
    }
    float hist = hs / fmaxf((float)cnt, 1.f);

    xs[0 * Dn + t] = 0.f;
    xs[1 * Dn + t] = cate_emb[likes[b] * Dn + t];
    xs[2 * Dn + t] = cate_emb[views[b] * Dn + t];
    xs[3 * Dn + t] = item_emb[(size_t)item_id[b] * Dn + t];
    xs[4 * Dn + t] = img;
    xs[5 * Dn + t] = hist;
    __syncthreads();

    float hp[Fn];
    #pragma unroll
    for (int n = 0; n < Fn; n++) hp[n] = 0.f;
    const float* Wh = gnn_W + h * (Dn * 32) + lane;
    #pragma unroll
    for (int c = 0; c < 4; c++) {
        float wv[32];
        #pragma unroll
        for (int q = 0; q < 32; q++) wv[q] = Wh[(c * 32 + q) * 32];
        #pragma unroll
        for (int n = 0; n < Fn; n++) {
            const float4* xv = reinterpret_cast<const float4*>(&xs[n * Dn + c * 32]);
            float a = hp[n];
            #pragma unroll
            for (int q8 = 0; q8 < 8; q8++) {
                float4 v = xv[q8];
                a = fmaf(v.x, wv[q8 * 4 + 0], a);
                a = fmaf(v.y, wv[q8 * 4 + 1], a);
                a = fmaf(v.z, wv[q8 * 4 + 2], a);
                a = fmaf(v.w, wv[q8 * 4 + 3], a);
            }
            hp[n] = a;
        }
    }

    float a1 = gnn_a[h * 64 + lane];
    float a2 = gnn_a[h * 64 + 32 + lane];
    float ei[Fn], ej[Fn];
    #pragma unroll
    for (int n = 0; n < Fn; n++) {
        float v1 = hp[n] * a1, v2 = hp[n] * a2;
        #pragma unroll
        for (int o = 16; o; o >>= 1) {
            v1 += __shfl_xor_sync(0xffffffffu, v1, o);
            v2 += __shfl_xor_sync(0xffffffffu, v2, o);
        }
        ei[n] = v1; ej[n] = v2;
    }

    float gnn[Fn];
    #pragma unroll
    for (int n = 0; n < Fn; n++) {
        float em[Fn], mx = -1e30f;
        #pragma unroll
        for (int m = 0; m < Fn; m++) {
            float e = ei[n] + ej[m];
            e = e > 0.f ? e : 0.2f * e;
            em[m] = e; mx = fmaxf(mx, e);
        }
        float ss = 0.f;
        #pragma unroll
        for (int m = 0; m < Fn; m++) { em[m] = expf(em[m] - mx); ss += em[m]; }
        float inv = 1.f / ss, acc = 0.f;
        #pragma unroll
        for (int m = 0; m < Fn; m++) acc = fmaf(em[m], hp[m], acc);
        float hn = acc * inv + xs[n * Dn + t];
        gnn[n] = hn > 0.f ? hn : expm1f(hn);
    }

    #pragma unroll
    for (int n = 0; n < Fn; n++) {
        float v = gnn[n];
        #pragma unroll
        for (int o = 16; o; o >>= 1) v += __shfl_xor_sync(0xffffffffu, v, o);
        if (!lane) red2[h * Fn + n] = v;
    }
    __syncthreads();

    float wv[Fn];
    {
        float z[Fn];
        #pragma unroll
        for (int n = 0; n < Fn; n++)
            z[n] = (red2[0 * Fn + n] + red2[1 * Fn + n] + red2[2 * Fn + n] + red2[3 * Fn + n]) * (1.f / Dn);
        float a[3];
        #pragma unroll
        for (int k = 0; k < 3; k++) {
            float v = se_b1[k];
            #pragma unroll
            for (int n = 0; n < Fn; n++) v = fmaf(z[n], se_w1[n * 3 + k], v);
            a[k] = fmaxf(v, 0.f);
        }
        #pragma unroll
        for (int f = 0; f < Fn; f++) {
            float v = se_b2[f];
            #pragma unroll
            for (int k = 0; k < 3; k++) v = fmaf(a[k], se_w2[k * 6 + f], v);
            wv[f] = 1.f / (1.f + expf(-v));
        }
    }

    __half* ch = g_c + (size_t)b * CINn;
    __half* sb = g_s + (size_t)b * Fn * Dn;
    #pragma unroll
    for (int n = 0; n < Fn; n++) {
        float v = gnn[n];
        ch[n * Dn + t] = __float2half(v);
        sb[n * Dn + t] = __float2half(v * wv[n]);
    }
}

// ---------------- weight prep: tiled transpose + fp16 ------------------------
// W[K][N] fp32 -> T[N][K] fp16, coalesced both sides via 32x32 smem tile.
__global__ __launch_bounds__(256) void k_wt(
    const float* __restrict__ W, __half* __restrict__ T, int K, int N)
{
    __shared__ float tile[32][33];
    int kb = blockIdx.x * 32, nb = blockIdx.y * 32;
    int tx = threadIdx.x & 31, ty = threadIdx.x >> 5;   // 32 x 8
    #pragma unroll
    for (int i = 0; i < 32; i += 8)
        tile[ty + i][tx] = W[(size_t)(kb + ty + i) * N + nb + tx];
    __syncthreads();
    #pragma unroll
    for (int i = 0; i < 32; i += 8)
        T[(size_t)(nb + ty + i) * K + kb + tx] = __float2half(tile[tx][ty + i]);
}
// bi_W[f][d][e] -> g_wb[f][e][d], tiled
__global__ __launch_bounds__(256) void k_wbi(const float* __restrict__ W)
{
    __shared__ float tile[32][33];
    int f = blockIdx.z;
    int db = blockIdx.x * 32, eb = blockIdx.y * 32;
    int tx = threadIdx.x & 31, ty = threadIdx.x >> 5;
    const float* Wf = W + (size_t)f * Dn * Dn;
    __half* Tf = g_wb + (size_t)f * Dn * Dn;
    #pragma unroll
    for (int i = 0; i < 32; i += 8)
        tile[ty + i][tx] = Wf[(db + ty + i) * Dn + eb + tx];
    __syncthreads();
    #pragma unroll
    for (int i = 0; i < 32; i += 8)
        Tf[(eb + ty + i) * Dn + db + tx] = __float2half(tile[tx][ty + i]);
}

// ---------------- shared GEMM constants --------------------------------------
#define BK 32
#define ROWB 80u

// ---------------- k_mma128: bilinear + fused pairs (coalesced epilogue) ------
#define BM 128
#define BN 128
#define OFF_A  0u
#define OFF_B  10240u
#define STAGEB 20480u
#define NSTAGE 4
#define SMEM_MMA (NSTAGE * STAGEB)
#define VP 132            // vid smem tile pitch in halves (128 + 4 pad)

__global__ __launch_bounds__(256, 1) void k_mma128(
    const __half* __restrict__ A, const __half* __restrict__ B,
    int K, int lda, long az, long bz)
{
    extern __shared__ char smem[];
    const uint32_t sbase = smem_u32(smem);
    const int tid = threadIdx.x;
    const int lane = tid & 31, wid = tid >> 5;
    const int wm = wid >> 2, wn = wid & 3;
    const int bm = blockIdx.y * BM, bn = blockIdx.x * BN;
    const int z = blockIdx.z;
    A += (size_t)z * az;
    B += (size_t)z * bz;

    float acc[4][4][4];
    #pragma unroll
    for (int mi = 0; mi < 4; mi++)
        #pragma unroll
        for (int ni = 0; ni < 4; ni++)
            #pragma unroll
            for (int q = 0; q < 4; q++) acc[mi][ni][q] = 0.f;

    const uint32_t a_base = (uint32_t)(wm * 64 + (lane & 15)) * ROWB + (uint32_t)((lane >> 4) * 16);
    const uint32_t b_base = (uint32_t)(wn * 32 + (lane & 7) + ((lane >> 4) << 3)) * ROWB
                          + (uint32_t)(((lane >> 3) & 1) * 16);

    const int nIter = K / BK;

    auto load_stage = [&](int buf, int k0) {
        uint32_t base = sbase + (uint32_t)buf * STAGEB;
        #pragma unroll
        for (int half = 0; half < 2; half++) {
            int e = tid + half * 256;
            int r = e >> 2, c = e & 3;
            uint32_t off = (uint32_t)r * ROWB + (uint32_t)c * 16;
            cp16(base + OFF_A + off, A + (size_t)(bm + r) * lda + k0 + c * 8);
            cp16(base + OFF_B + off, B + (size_t)(bn + r) * K   + k0 + c * 8);
        }
    };

    load_stage(0, 0);
    cp_commit();
    load_stage(1, BK);
    cp_commit();
    load_stage(2, 2 * BK);
    cp_commit();

    for (int it = 0; it < nIter; it++) {
        if (it + 3 < nIter) {
            load_stage((it + 3) & 3, (it + 3) * BK);
            cp_commit();
            cp_wait<3>();
        } else if (it + 2 < nIter) {
            cp_wait<2>();
        } else if (it + 1 < nIter) {
            cp_wait<1>();
        } else {
            cp_wait<0>();
        }
        __syncthreads();

        uint32_t base = sbase + (uint32_t)(it & 3) * STAGEB;
        #pragma unroll
        for (int ks = 0; ks < 2; ks++) {
            uint32_t koff = (uint32_t)ks * 32;
            uint32_t a[4][4], bb[2][4];
            #pragma unroll
            for (int mi = 0; mi < 4; mi++)
                ldsm4(a[mi], base + OFF_A + a_base + (uint32_t)mi * 16 * ROWB + koff);
            #pragma unroll
            for (int nq = 0; nq < 2; nq++)
                ldsm4(bb[nq], base + OFF_B + b_base + (uint32_t)nq * 16 * ROWB + koff);
            #pragma unroll
            for (int mi = 0; mi < 4; mi++)
                #pragma unroll
                for (int ni = 0; ni < 4; ni++)
                    mma_fp16(acc[mi][ni], a[mi], &bb[ni >> 1][(ni & 1) * 2]);
        }
        __syncthreads();
    }
    __syncthreads();

    // stage vid tile into smem (fp16, pitch VP)
    __half* vt = reinterpret_cast<__half*>(smem);
    #pragma unroll
    for (int ni = 0; ni < 4; ni++) {
        int col = wn * 32 + ni * 8 + (lane & 3) * 2;
        #pragma unroll
        for (int mi = 0; mi < 4; mi++) {
            int r0 = wm * 64 + mi * 16 + (lane >> 2);
            #pragma unroll
            for (int half = 0; half < 2; half++) {
                int row = r0 + half * 8;
                vt[row * VP + col]     = __float2half(acc[mi][ni][half * 2 + 0]);
                vt[row * VP + col + 1] = __float2half(acc[mi][ni][half * 2 + 1]);
            }
        }
    }
    __syncthreads();

    // coalesced pair writes: c[b, pair(z,j), :] = vid * s[b, j, :]
    const int poff = z * (11 - z) / 2;
    for (int j = z + 1; j < Fn; j++) {
        int p = poff + j - z - 1;
        for (int idx = tid; idx < 128 * 64; idx += 256) {
            int row = idx >> 6, c2 = idx & 63;
            size_t gb = (size_t)(bm + row);
            __half2 vv = *reinterpret_cast<__half2*>(&vt[row * VP + c2 * 2]);
            __half2 sv = *reinterpret_cast<const __half2*>(&g_s[gb * (Fn * Dn) + j * Dn + c2 * 2]);
            float v0 = __half2float(__low2half(vv))  * __half2float(__low2half(sv));
            float v1 = __half2float(__high2half(vv)) * __half2float(__high2half(sv));
            *reinterpret_cast<__half2*>(&g_c[gb * CINn + Fn * Dn + p * Dn + c2 * 2]) =
                __halves2half2(__float2half(v0), __float2half(v1));
        }
    }
}

// ---------------- k_mma256: BN=256, warp tile 64x64 (MLP layers) -------------
#define BM2 128
#define BN2 256
#define OFF_A2  0u
#define OFF_B2  10240u
#define STAGEB2 30720u
#define NSTAGE2 4
#define SMEM_MMA2 (NSTAGE2 * STAGEB2)

__global__ __launch_bounds__(256, 1) void k_mma256(
    const __half* __restrict__ A, const __half* __restrict__ B,
    int K,
    float* __restrict__ outf, __half* __restrict__ oh, int ldc,
    const float* __restrict__ bias, const float* __restrict__ bng,
    const float* __restrict__ bnb, int mode)
{
    extern __shared__ char smem[];
    const uint32_t sbase = smem_u32(smem);
    const int tid = threadIdx.x;
    const int lane = tid & 31, wid = tid >> 5;
    const int wm = wid >> 2, wn = wid & 3;
    const int bm = blockIdx.y * BM2, bn = blockIdx.x * BN2;

    float acc[4][8][4];
    #pragma unroll
    for (int mi = 0; mi < 4; mi++)
        #pragma unroll
        for (int ni = 0; ni < 8; ni++)
            #pragma unroll
            for (int q = 0; q < 4; q++) acc[mi][ni][q] = 0.f;

    const uint32_t a_base = (uint32_t)(wm * 64 + (lane & 15)) * ROWB + (uint32_t)((lane >> 4) * 16);
    const uint32_t b_base = (uint32_t)(wn * 64 + (lane & 7) + ((lane >> 4) << 3)) * ROWB
                          + (uint32_t)(((lane >> 3) & 1) * 16);

    const int nIter = K / BK;

    auto load_stage = [&](int buf, int k0) {
        uint32_t base = sbase + (uint32_t)buf * STAGEB2;
        #pragma unroll
        for (int half = 0; half < 2; half++) {
            int e = tid + half * 256;
            int r = e >> 2, c = e & 3;
            uint32_t off = (uint32_t)r * ROWB + (uint32_t)c * 16;
            cp16(base + OFF_A2 + off, A + (size_t)(bm + r) * K + k0 + c * 8);
        }
        #pragma unroll
        for (int half = 0; half < 4; half++) {
            int e = tid + half * 256;
            int r = e >> 2, c = e & 3;
            uint32_t off = (uint32_t)r * ROWB + (uint32_t)c * 16;
            cp16(base + OFF_B2 + off, B + (size_t)(bn + r) * K + k0 + c * 8);
        }
    };

    load_stage(0, 0);
    cp_commit();
    load_stage(1, BK);
    cp_commit();
    load_stage(2, 2 * BK);
    cp_commit();

    for (int it = 0; it < nIter; it++) {
        if (it + 3 < nIter) {
            load_stage((it + 3) & 3, (it + 3) * BK);
            cp_commit();
            cp_wait<3>();
        } else if (it + 2 < nIter) {
            cp_wait<2>();
        } else if (it + 1 < nIter) {
            cp_wait<1>();
        } else {
            cp_wait<0>();
        }
        __syncthreads();

        uint32_t base = sbase + (uint32_t)(it & 3) * STAGEB2;
        #pragma unroll
        for (int ks = 0; ks < 2; ks++) {
            uint32_t koff = (uint32_t)ks * 32;
            uint32_t a[4][4], bb[4][4];
            #pragma unroll
            for (int mi = 0; mi < 4; mi++)
                ldsm4(a[mi], base + OFF_A2 + a_base + (uint32_t)mi * 16 * ROWB + koff);
            #pragma unroll
            for (int nq = 0; nq < 4; nq++)
                ldsm4(bb[nq], base + OFF_B2 + b_base + (uint32_t)nq * 16 * ROWB + koff);
            #pragma unroll
            for (int mi = 0; mi < 4; mi++)
                #pragma unroll
                for (int ni = 0; ni < 8; ni++)
                    mma_fp16(acc[mi][ni], a[mi], &bb[ni >> 1][(ni & 1) * 2]);
        }
        __syncthreads();
    }

    const float bnscale = 0.999995000037499688f;  // 1/sqrt(1+1e-5)
    #pragma unroll
    for (int ni = 0; ni < 8; ni++) {
        int col = bn + wn * 64 + ni * 8 + (lane & 3) * 2;
        float bi0 = bias[col],         bi1 = bias[col + 1];
        float g0 = bng[col] * bnscale, g1 = bng[col + 1] * bnscale;
        float bb0 = bnb[col],          bb1 = bnb[col + 1];
        #pragma unroll
        for (int mi = 0; mi < 4; mi++) {
            int r0 = bm + wm * 64 + mi * 16 + (lane >> 2);
            #pragma unroll
            for (int half = 0; half < 2; half++) {
                int row = r0 + half * 8;
                float v0 = acc[mi][ni][half * 2 + 0];
                float v1 = acc[mi][ni][half * 2 + 1];
                v0 = (v0 + bi0) * g0 + bb0;
                v1 = (v1 + bi1) * g1 + bb1;
                v0 = 0.5f * v0 * (1.f + erff(v0 * 0.70710678118654752f));
                v1 = 0.5f * v1 * (1.f + erff(v1 * 0.70710678118654752f));
                if (mode == 2) {
                    outf[(size_t)row * ldc + col]     = v0;
                    outf[(size_t)row * ldc + col + 1] = v1;
                } else {
                    oh[(size_t)row * ldc + col]     = __float2half(v0);
                    oh[(size_t)row * ldc + col + 1] = __float2half(v1);
                }
            }
        }
    }
}

// ---------------- K5: final dot + sigmoid ------------------------------------
__global__ __launch_bounds__(256) void k_final(
    const float* __restrict__ w3, const float* __restrict__ b3,
    float* __restrict__ out)
{
    int warp = threadIdx.x >> 5, lane = threadIdx.x & 31;
    int b = blockIdx.x * 8 + warp;
    const float* hh = g_h2 + (size_t)b * H2N;
    float acc = 0.f;
    #pragma unroll
    for (int i = 0; i < 8; i++) acc = fmaf(hh[lane + i * 32], w3[lane + i * 32], acc);
    #pragma unroll
    for (int o = 16; o; o >>= 1) acc += __shfl_xor_sync(0xffffffffu, acc, o);
    if (!lane) out[b] = 1.f / (1.f + expf(-(acc + b3[0])));
}

// ---------------- launch -----------------------------------------------------
extern "C" void kernel_launch(void* const* d_in, const int* in_sizes, int n_in,
                              void* d_out, int out_size)
{
    const int*   item_id  = (const int*)  d_in[0];
    const float* item_mm  = (const float*)d_in[1];
    const int*   likes    = (const int*)  d_in[2];
    const int*   views    = (const int*)  d_in[3];
    const int*   item_seq = (const int*)  d_in[4];
    const float* item_emb = (const float*)d_in[5];
    const float* cate_emb = (const float*)d_in[6];
    const float* mm_w     = (const float*)d_in[7];
    const float* mm_b     = (const float*)d_in[8];
    const float* ln_g     = (const float*)d_in[9];
    const float* ln_b     = (const float*)d_in[10];
    const float* gnn_W    = (const float*)d_in[11];
    const float* gnn_a    = (const float*)d_in[12];
    const float* se_w1    = (const float*)d_in[13];
    const float* se_b1    = (const float*)d_in[14];
    const float* se_w2    = (const float*)d_in[15];
    const float* se_b2    = (const float*)d_in[16];
    const float* bi_W     = (const float*)d_in[17];
    const float* w1       = (const float*)d_in[18];
    const float* b1       = (const float*)d_in[19];
    const float* bn1g     = (const float*)d_in[20];
    const float* bn1b     = (const float*)d_in[21];
    const float* w2       = (const float*)d_in[22];
    const float* b2       = (const float*)d_in[23];
    const float* bn2g     = (const float*)d_in[24];
    const float* bn2b     = (const float*)d_in[25];
    const float* w3       = (const float*)d_in[26];
    const float* b3       = (const float*)d_in[27];
    float* out = (float*)d_out;

    float *ph2;
    __half *ps, *pc, *ph1, *pw1, *pw2;
    cudaGetSymbolAddress((void**)&ps,   g_s);
    cudaGetSymbolAddress((void**)&ph2,  g_h2);
    cudaGetSymbolAddress((void**)&pc,   g_c);
    cudaGetSymbolAddress((void**)&ph1,  g_h1);
    cudaGetSymbolAddress((void**)&pw1,  g_w1t);
    cudaGetSymbolAddress((void**)&pw2,  g_w2t);
    __half* pwb;
    cudaGetSymbolAddress((void**)&pwb,  g_wb);

    cudaFuncSetAttribute(k_mma128, cudaFuncAttributeMaxDynamicSharedMemorySize, SMEM_MMA);
    cudaFuncSetAttribute(k_mma256, cudaFuncAttributeMaxDynamicSharedMemorySize, SMEM_MMA2);

    // weight prep (tiled transpose + fp16)
    {
        dim3 g1(CINn / 32, H1N / 32);
        k_wt<<<g1, 256>>>(w1, pw1, CINn, H1N);
        dim3 g2(H1N / 32, H2N / 32);
        k_wt<<<g2, 256>>>(w2, pw2, H1N, H2N);
        dim3 g3(Dn / 32, Dn / 32, 5);
        k_wbi<<<g3, 256>>>(bi_W);
    }

    // fused features + GNN + SE
    k_feat_gnn<<<Bn, 128>>>(item_id, item_mm, likes, views, item_seq,
                            item_emb, cate_emb, mm_w, mm_b, ln_g, ln_b,
                            gnn_W, gnn_a, se_w1, se_b1, se_w2, se_b2);

    // bilinear + fused pairs: z = field i; writes c[:, 768:] directly
    {
        dim3 grid(1, Bn / BM, 5);
        k_mma128<<<grid, 256, SMEM_MMA>>>(ps, pwb, Dn, Fn * Dn, Dn, (long)Dn * Dn);
    }

    // layer 1: c @ w1 (+bias,bn,gelu) -> h1 (fp16)
    {
        dim3 grid(H1N / BN2, Bn / BM2, 1);
        k_mma256<<<grid, 256, SMEM_MMA2>>>(pc, pw1, CINn,
                                           nullptr, ph1, H1N, b1, bn1g, bn1b, 1);
    }
    // layer 2: h1 @ w2 (+bias,bn,gelu) -> h2 (fp32)
    {
        dim3 grid(H2N / BN2, Bn / BM2, 1);
        k_mma256<<<grid, 256, SMEM_MMA2>>>(ph1, pw2, H1N,
                                           ph2, nullptr, H2N, b2, bn2g, bn2b, 2);
    }
    k_final<<<Bn / 8, 256>>>(w3, b3, out);
}